// round 1
// baseline (speedup 1.0000x reference)
#include <cuda_runtime.h>
#include <math.h>

#define NB 4
#define CIN 3
#define NC 64
#define NC2 128
#define H0 256
#define W0 256
#define NPIX0 (H0*W0)
#define HP 264
#define NP (HP*HP)      /* 69696 */
#define NR 64           /* kept ky modes: 0..31 and 232..263 */
#define NM 32           /* kept kx modes */
#define SPW (64*64*32*32)

// ---------------- scratch (device globals; no runtime allocation) ----------
__device__ float  g_x  [NB*NC *NP];     // current activations, padded
__device__ float  g_y  [NB*NC *NP];     // conv branch temp
__device__ float  g_t  [NB*NC2*NP];     // mlp hidden (128 ch)
__device__ float  g_hbr[NB*NC *NP];     // local branch output
__device__ float2 g_T1 [NB*NC*NR*HP];   // row-DFT partial
__device__ float2 g_xf [NB*NC*NR*NM];   // forward spectrum (kept modes)
__device__ float2 g_of [NB*NC*NR*NM];   // channel-mixed spectrum
__device__ float2 g_U  [NB*NC*HP*NM];   // inverse row stage
__device__ float2 g_Fy [NR*HP];         // (cos, -sin) for ky modes
__device__ float2 g_Fx [NM*HP];         // (cos, -sin) for kx modes

__device__ __forceinline__ float gelu_exact(float v) {
    return 0.5f * v * (1.0f + erff(v * 0.70710678118654752440f));
}

// ---------------- init ------------------------------------------------------
__global__ void k_tables() {
    int idx = blockIdx.x * 256 + threadIdx.x;
    if (idx < NR*HP) {
        int r = idx / HP, y = idx % HP;
        int ky = (r < 32) ? r : r + 200;           // 232..263
        int m = (ky * y) % HP;
        double a = 6.283185307179586 * (double)m / (double)HP;
        g_Fy[idx] = make_float2((float)cos(a), (float)(-sin(a)));
    } else if (idx < NR*HP + NM*HP) {
        int j = idx - NR*HP;
        int k = j / HP, xx = j % HP;
        int m = (k * xx) % HP;
        double a = 6.283185307179586 * (double)m / (double)HP;
        g_Fx[j] = make_float2((float)cos(a), (float)(-sin(a)));
    }
}

__global__ void k_zero_x() {
    int n = NB*NC*NP;
    for (int i = blockIdx.x * 256 + threadIdx.x; i < n; i += gridDim.x * 256)
        g_x[i] = 0.0f;
}

// ---------------- lift: 5 -> 32 (GELU) -> 64, write into padded buffer -----
__global__ void __launch_bounds__(256) k_lift(
    const float* __restrict__ x,
    const float* __restrict__ w1, const float* __restrict__ b1,
    const float* __restrict__ w2, const float* __restrict__ b2)
{
    __shared__ float sw1[32*5], sb1[32], sw2[64*32], sb2[64];
    for (int i = threadIdx.x; i < 160;  i += 256) sw1[i] = w1[i];
    for (int i = threadIdx.x; i < 32;   i += 256) sb1[i] = b1[i];
    for (int i = threadIdx.x; i < 2048; i += 256) sw2[i] = w2[i];
    for (int i = threadIdx.x; i < 64;   i += 256) sb2[i] = b2[i];
    __syncthreads();
    int b = blockIdx.y;
    int p = blockIdx.x * 256 + threadIdx.x;   // 0..65535
    int i = p >> 8, j = p & 255;
    float f[5];
    f[0] = x[(b*CIN + 0)*NPIX0 + p];
    f[1] = x[(b*CIN + 1)*NPIX0 + p];
    f[2] = x[(b*CIN + 2)*NPIX0 + p];
    f[3] = (float)i * (1.0f/255.0f);
    f[4] = (float)j * (1.0f/255.0f);
    float h[32];
    #pragma unroll
    for (int c1 = 0; c1 < 32; c1++) {
        float v = sb1[c1];
        #pragma unroll
        for (int q = 0; q < 5; q++) v = fmaf(sw1[c1*5+q], f[q], v);
        h[c1] = gelu_exact(v);
    }
    int base = b*NC*NP + i*HP + j;
    for (int c2 = 0; c2 < 64; c2++) {
        float v = sb2[c2];
        #pragma unroll
        for (int c1 = 0; c1 < 32; c1++) v = fmaf(sw2[c2*32+c1], h[c1], v);
        g_x[base + c2*NP] = v;
    }
}

// ---------------- 1x1 conv (channel GEMM), optional GELU -------------------
template<int CI, int CO, bool DOGELU>
__global__ void __launch_bounds__(256) k_conv1x1(
    const float* __restrict__ in, float* __restrict__ out,
    const float* __restrict__ W, const float* __restrict__ B)
{
    __shared__ float ws[CI*CO];
    __shared__ float bs[CO];
    for (int i = threadIdx.x; i < CI*CO; i += 256) ws[i] = W[i];
    if (threadIdx.x < CO) bs[threadIdx.x] = B[threadIdx.x];
    __syncthreads();
    int p = blockIdx.x * 256 + threadIdx.x;
    if (p >= NP) return;
    const float* inb = in + blockIdx.y * (CI*NP) + p;
    float xv[CI];
    #pragma unroll
    for (int ci = 0; ci < CI; ci++) xv[ci] = inb[ci*NP];
    float* outb = out + blockIdx.y * (CO*NP) + p;
    for (int co = 0; co < CO; co++) {
        float acc = bs[co];
        #pragma unroll
        for (int ci = 0; ci < CI; ci++) acc = fmaf(ws[co*CI+ci], xv[ci], acc);
        if (DOGELU) acc = gelu_exact(acc);
        outb[co*NP] = acc;
    }
}

// ---------------- S1: row DFT: T1[bc,r,x] = sum_y x[bc,y,x] * Fy[r,y] ------
__global__ void k_dft_rows() {
    int bc = blockIdx.x, rg = blockIdx.y;        // 8 r's per block
    __shared__ float2 fy[8*HP];
    for (int idx = threadIdx.x; idx < 8*HP; idx += blockDim.x)
        fy[idx] = g_Fy[(rg*8)*HP + idx];
    __syncthreads();
    int x = threadIdx.x;                          // 0..263
    const float* img = g_x + bc*NP + x;
    float ar[8] = {0,0,0,0,0,0,0,0};
    float ai[8] = {0,0,0,0,0,0,0,0};
    for (int y = 0; y < HP; y++) {
        float v = img[y*HP];
        #pragma unroll
        for (int rl = 0; rl < 8; rl++) {
            float2 f = fy[rl*HP + y];
            ar[rl] = fmaf(v, f.x, ar[rl]);
            ai[rl] = fmaf(v, f.y, ai[rl]);
        }
    }
    #pragma unroll
    for (int rl = 0; rl < 8; rl++)
        g_T1[(bc*NR + rg*8 + rl)*HP + x] = make_float2(ar[rl], ai[rl]);
}

// ---------------- S2: col DFT: xf[bc,r,k] = sum_x T1[bc,r,x]*Fx[k,x] -------
__global__ void k_dft_cols() {
    int bc = blockIdx.x, rg = blockIdx.y;
    __shared__ float2 t1s[8*HP];
    for (int idx = threadIdx.x; idx < 8*HP; idx += 256)
        t1s[idx] = g_T1[(bc*NR + rg*8)*HP + idx];
    __syncthreads();
    int rl = threadIdx.x & 7, k = threadIdx.x >> 3;   // 8 r x 32 k
    float ar = 0.f, ai = 0.f;
    for (int x = 0; x < HP; x++) {
        float2 a = t1s[rl*HP + x];
        float2 f = __ldg(&g_Fx[k*HP + x]);
        ar += a.x*f.x - a.y*f.y;
        ai += a.x*f.y + a.y*f.x;
    }
    g_xf[(bc*NR + rg*8 + rl)*NM + k] = make_float2(ar, ai);
}

// ---------------- S3: per-mode 64x64 complex channel mix -------------------
__global__ void __launch_bounds__(256) k_chanmix(
    const float* __restrict__ w1r, const float* __restrict__ w1i,
    const float* __restrict__ w2r, const float* __restrict__ w2i)
{
    int r = blockIdx.x >> 5, k = blockIdx.x & 31;
    __shared__ float wre[NC*NC];
    __shared__ float wim[NC*NC];
    __shared__ float2 xs[NB][NC];
    const float* wr; const float* wi; int m1;
    if (r < 32) { wr = w1r; wi = w1i; m1 = r; }
    else        { wr = w2r; wi = w2i; m1 = r - 32; }
    int woff = m1*32 + k;
    for (int idx = threadIdx.x; idx < NC*NC; idx += 256) {
        wre[idx] = wr[idx*1024 + woff];   // weight layout [i][o][32][32]
        wim[idx] = wi[idx*1024 + woff];
    }
    {
        int b = threadIdx.x >> 6, i = threadIdx.x & 63;
        xs[b][i] = g_xf[((b*NC + i)*NR + r)*NM + k];
    }
    __syncthreads();
    int o = threadIdx.x & 63, b = threadIdx.x >> 6;
    float ar = 0.f, ai = 0.f;
    #pragma unroll 4
    for (int i = 0; i < NC; i++) {
        float2 xv = xs[b][i];
        float wrv = wre[i*64 + o], wiv = wim[i*64 + o];
        ar += xv.x*wrv - xv.y*wiv;
        ai += xv.x*wiv + xv.y*wrv;
    }
    g_of[((b*NC + o)*NR + r)*NM + k] = make_float2(ar, ai);
}

// ---------------- S4: inverse along ky (complex ifft, 64 nonzero bins) -----
__global__ void k_idft_rows() {
    int bo = blockIdx.x;
    __shared__ float2 os[NR*NM];
    for (int idx = threadIdx.x; idx < NR*NM; idx += 256)
        os[idx] = g_of[bo*(NR*NM) + idx];
    __syncthreads();
    int k = threadIdx.x & 31, y0 = threadIdx.x >> 5;
    for (int it = 0; it < 33; it++) {
        int y = y0 + it*8;    // covers 0..263 exactly
        float ar = 0.f, ai = 0.f;
        #pragma unroll 8
        for (int r = 0; r < NR; r++) {
            float2 f = __ldg(&g_Fy[r*HP + y]);  // forward = (cos,-sin); inverse uses (cos,+sin)
            float c = f.x, s = -f.y;
            float2 o = os[r*NM + k];
            ar += o.x*c - o.y*s;
            ai += o.x*s + o.y*c;
        }
        g_U[(bo*HP + y)*NM + k] = make_float2(ar*(1.0f/HP), ai*(1.0f/HP));
    }
}

// ---------------- S5: real inverse along kx + add local branch -------------
__global__ void k_idft_cols_add() {
    int y  = blockIdx.x;       // 0..263
    int bo = blockIdx.y;       // 0..255
    __shared__ float2 us[NM];
    if (threadIdx.x < NM) us[threadIdx.x] = g_U[(bo*HP + y)*NM + threadIdx.x];
    __syncthreads();
    int x = threadIdx.x;       // 0..263
    // c2r convention: Im of bin 0 is dropped; bins 1..31 doubled (no Nyquist).
    float s = us[0].x;
    #pragma unroll 8
    for (int k = 1; k < NM; k++) {
        float2 f = __ldg(&g_Fx[k*HP + x]);   // (cos, -sin)
        s += 2.0f * (us[k].x*f.x + us[k].y*f.y);  // Re*cos - Im*sin
    }
    int idx = bo*NP + y*HP + x;
    g_x[idx] = g_hbr[idx] + s * (1.0f/HP);
}

// ---------------- crop to [4,64,256,256] ------------------------------------
__global__ void k_crop(float* __restrict__ out) {
    int idx = blockIdx.x * 256 + threadIdx.x;   // 16777216 total
    int j  = idx & 255;
    int i  = (idx >> 8) & 255;
    int bc = idx >> 16;
    out[idx] = g_x[bc*NP + i*HP + j];
}

// ---------------- launch -----------------------------------------------------
extern "C" void kernel_launch(void* const* d_in, const int* in_sizes, int n_in,
                              void* d_out, int out_size)
{
    const float* x   = (const float*)d_in[0];
    const float* lw1 = (const float*)d_in[1];
    const float* lb1 = (const float*)d_in[2];
    const float* lw2 = (const float*)d_in[3];
    const float* lb2 = (const float*)d_in[4];
    const float* cw  = (const float*)d_in[5];
    const float* cb  = (const float*)d_in[6];
    const float* m1w = (const float*)d_in[7];
    const float* m1b = (const float*)d_in[8];
    const float* m2w = (const float*)d_in[9];
    const float* m2b = (const float*)d_in[10];
    const float* s1r = (const float*)d_in[11];
    const float* s1i = (const float*)d_in[12];
    const float* s2r = (const float*)d_in[13];
    const float* s2i = (const float*)d_in[14];
    float* out = (float*)d_out;

    float *px, *py, *pt, *ph;
    cudaGetSymbolAddress((void**)&px, g_x);
    cudaGetSymbolAddress((void**)&py, g_y);
    cudaGetSymbolAddress((void**)&pt, g_t);
    cudaGetSymbolAddress((void**)&ph, g_hbr);

    k_tables<<<99, 256>>>();
    k_zero_x<<<4096, 256>>>();
    k_lift<<<dim3(256, NB), 256>>>(x, lw1, lb1, lw2, lb2);

    const int GP = (NP + 255) / 256;   // 273
    for (int L = 0; L < 3; L++) {
        // local branch: conv -> mlp1+gelu -> mlp2
        k_conv1x1<64, 64,  false><<<dim3(GP, NB), 256>>>(px, py, cw  + L*64*64,  cb  + L*64);
        k_conv1x1<64, 128, true ><<<dim3(GP, NB), 256>>>(py, pt, m1w + L*128*64, m1b + L*128);
        k_conv1x1<128,64,  false><<<dim3(GP, NB), 256>>>(pt, ph, m2w + L*64*128, m2b + L*64);
        // spectral branch
        k_dft_rows<<<dim3(NB*NC, 8), HP>>>();
        k_dft_cols<<<dim3(NB*NC, 8), 256>>>();
        k_chanmix<<<NR*NM, 256>>>(s1r + L*SPW, s1i + L*SPW, s2r + L*SPW, s2i + L*SPW);
        k_idft_rows<<<NB*NC, 256>>>();
        k_idft_cols_add<<<dim3(HP, NB*NC), HP>>>();
    }

    k_crop<<<(NB*NC*H0*W0)/256, 256>>>(out);
}

// round 2
// speedup vs baseline: 1.2695x; 1.2695x over previous
#include <cuda_runtime.h>
#include <math.h>

#define NB 4
#define CIN 3
#define NC 64
#define H0 256
#define W0 256
#define NPIX0 (H0*W0)
#define HP 264
#define NP (HP*HP)      /* 69696 */
#define NR 64           /* kept ky modes: 0..31 and 232..263 */
#define NM 32           /* kept kx modes */
#define SPW (64*64*32*32)
#define INV_HP (1.0f/264.0f)

// ---------------- scratch (device globals; no runtime allocation) ----------
__device__ float  g_x  [NB*NC*NP];     // current activations, padded
__device__ float  g_hbr[NB*NC*NP];     // local branch output
__device__ float2 g_T1 [NB*NC*NR*HP];  // row-DFT partial
__device__ float2 g_xf [NB*NC*NR*NM];  // forward spectrum (kept modes)
__device__ float2 g_of [NB*NC*NR*NM];  // channel-mixed spectrum
__device__ float2 g_U  [NB*NC*HP*NM];  // inverse row stage
__device__ float2 g_Fy [NR*HP];        // (cos, -sin) for kept ky modes
__device__ float2 g_Fx [NM*HP];        // (cos, -sin), [k][x]
__device__ float2 g_FxT[HP*NM];        // transposed:   [x][k]

__device__ __forceinline__ float gelu_exact(float v) {
    return 0.5f * v * (1.0f + erff(v * 0.70710678118654752440f));
}

// ---------------- init ------------------------------------------------------
__global__ void k_tables() {
    int idx = blockIdx.x * 256 + threadIdx.x;
    if (idx < NR*HP) {
        int r = idx / HP, y = idx % HP;
        int ky = (r < 32) ? r : r + 200;           // 232..263
        int m = (ky * y) % HP;
        double a = 6.283185307179586 * (double)m / (double)HP;
        g_Fy[idx] = make_float2((float)cos(a), (float)(-sin(a)));
    } else if (idx < NR*HP + NM*HP) {
        int j = idx - NR*HP;
        int k = j / HP, xx = j % HP;
        int m = (k * xx) % HP;
        double a = 6.283185307179586 * (double)m / (double)HP;
        float2 f = make_float2((float)cos(a), (float)(-sin(a)));
        g_Fx[j] = f;
        g_FxT[xx*NM + k] = f;
    }
}

__global__ void k_zero_x() {
    int n = NB*NC*NP;
    for (int i = blockIdx.x * 256 + threadIdx.x; i < n; i += gridDim.x * 256)
        g_x[i] = 0.0f;
}

// ---------------- lift: 5 -> 32 (GELU) -> 64, write into padded buffer -----
__global__ void __launch_bounds__(256) k_lift(
    const float* __restrict__ x,
    const float* __restrict__ w1, const float* __restrict__ b1,
    const float* __restrict__ w2, const float* __restrict__ b2)
{
    __shared__ float sw1[32*5], sb1[32], sw2[64*32], sb2[64];
    for (int i = threadIdx.x; i < 160;  i += 256) sw1[i] = w1[i];
    for (int i = threadIdx.x; i < 32;   i += 256) sb1[i] = b1[i];
    for (int i = threadIdx.x; i < 2048; i += 256) sw2[i] = w2[i];
    for (int i = threadIdx.x; i < 64;   i += 256) sb2[i] = b2[i];
    __syncthreads();
    int b = blockIdx.y;
    int p = blockIdx.x * 256 + threadIdx.x;   // 0..65535
    int i = p >> 8, j = p & 255;
    float f[5];
    f[0] = x[(b*CIN + 0)*NPIX0 + p];
    f[1] = x[(b*CIN + 1)*NPIX0 + p];
    f[2] = x[(b*CIN + 2)*NPIX0 + p];
    f[3] = (float)i * (1.0f/255.0f);
    f[4] = (float)j * (1.0f/255.0f);
    float h[32];
    #pragma unroll
    for (int c1 = 0; c1 < 32; c1++) {
        float v = sb1[c1];
        #pragma unroll
        for (int q = 0; q < 5; q++) v = fmaf(sw1[c1*5+q], f[q], v);
        h[c1] = gelu_exact(v);
    }
    int base = b*NC*NP + i*HP + j;
    for (int c2 = 0; c2 < 64; c2++) {
        float v = sb2[c2];
        #pragma unroll
        for (int c1 = 0; c1 < 32; c1++) v = fmaf(sw2[c2*32+c1], h[c1], v);
        g_x[base + c2*NP] = v;
    }
}

// ---------------- fused local branch: conv64->64, mlp 64->128 (gelu), 128->64
// 64-pixel tiles, 16x16 threads, 4x4 register micro-tiles.
__global__ void __launch_bounds__(256, 2) k_local(
    const float* __restrict__ in, float* __restrict__ out,
    const float* __restrict__ W1, const float* __restrict__ B1,
    const float* __restrict__ W2, const float* __restrict__ B2,
    const float* __restrict__ W3, const float* __restrict__ B3)
{
    extern __shared__ __align__(16) float sm_local[];
    float* sX = sm_local;           // 64x64
    float* sY = sm_local + 4096;    // 64x64
    float* sT = sm_local + 8192;    // 128x64
    float* sW = sm_local + 16384;   // up to 8704 floats
    const int tid = threadIdx.x;
    const int ty = tid >> 4, tx = tid & 15;
    const int r0 = ty * 4, x0 = tx * 4;
    const int base = blockIdx.y * (NC*NP) + blockIdx.x * 64;

    // load X tile [c][px] and W1^T [ci][co] (pad 68)
    #pragma unroll
    for (int i = 0; i < 16; i++) {
        int idx = tid + i*256;
        sX[idx] = in[base + (idx >> 6)*NP + (idx & 63)];
        sW[(idx & 63)*68 + (idx >> 6)] = W1[idx];
    }
    __syncthreads();

    float acc[4][4];
    // ---- stage 1: Y = W1 X + b1
    #pragma unroll
    for (int i = 0; i < 4; i++) {
        float bv = B1[r0 + i];
        #pragma unroll
        for (int j = 0; j < 4; j++) acc[i][j] = bv;
    }
    for (int k = 0; k < 64; k++) {
        float4 a = *(const float4*)&sW[k*68 + r0];
        float4 b = *(const float4*)&sX[k*64 + x0];
        const float av[4] = {a.x, a.y, a.z, a.w};
        const float bv[4] = {b.x, b.y, b.z, b.w};
        #pragma unroll
        for (int i = 0; i < 4; i++)
            #pragma unroll
            for (int j = 0; j < 4; j++)
                acc[i][j] = fmaf(av[i], bv[j], acc[i][j]);
    }
    #pragma unroll
    for (int i = 0; i < 4; i++)
        *(float4*)&sY[(r0+i)*64 + x0] = make_float4(acc[i][0], acc[i][1], acc[i][2], acc[i][3]);
    __syncthreads();

    // load W2^T [ci=64][co=128] (pad 132)
    #pragma unroll
    for (int i = 0; i < 32; i++) {
        int idx = tid + i*256;
        sW[(idx & 63)*132 + (idx >> 6)] = W2[idx];
    }
    __syncthreads();

    // ---- stage 2: T = gelu(W2 Y + b2), 128 rows in two halves
    #pragma unroll
    for (int h = 0; h < 2; h++) {
        #pragma unroll
        for (int i = 0; i < 4; i++) {
            float bv = B2[h*64 + r0 + i];
            #pragma unroll
            for (int j = 0; j < 4; j++) acc[i][j] = bv;
        }
        for (int k = 0; k < 64; k++) {
            float4 a = *(const float4*)&sW[k*132 + h*64 + r0];
            float4 b = *(const float4*)&sY[k*64 + x0];
            const float av[4] = {a.x, a.y, a.z, a.w};
            const float bv[4] = {b.x, b.y, b.z, b.w};
            #pragma unroll
            for (int i = 0; i < 4; i++)
                #pragma unroll
                for (int j = 0; j < 4; j++)
                    acc[i][j] = fmaf(av[i], bv[j], acc[i][j]);
        }
        #pragma unroll
        for (int i = 0; i < 4; i++) {
            float4 r = make_float4(gelu_exact(acc[i][0]), gelu_exact(acc[i][1]),
                                   gelu_exact(acc[i][2]), gelu_exact(acc[i][3]));
            *(float4*)&sT[(h*64 + r0 + i)*64 + x0] = r;
        }
    }
    __syncthreads();

    // load W3^T [ci=128][co=64] (pad 68)
    #pragma unroll
    for (int i = 0; i < 32; i++) {
        int idx = tid + i*256;
        sW[(idx & 127)*68 + (idx >> 7)] = W3[idx];
    }
    __syncthreads();

    // ---- stage 3: OUT = W3 T + b3 (K=128)
    #pragma unroll
    for (int i = 0; i < 4; i++) {
        float bv = B3[r0 + i];
        #pragma unroll
        for (int j = 0; j < 4; j++) acc[i][j] = bv;
    }
    for (int k = 0; k < 128; k++) {
        float4 a = *(const float4*)&sW[k*68 + r0];
        float4 b = *(const float4*)&sT[k*64 + x0];
        const float av[4] = {a.x, a.y, a.z, a.w};
        const float bv[4] = {b.x, b.y, b.z, b.w};
        #pragma unroll
        for (int i = 0; i < 4; i++)
            #pragma unroll
            for (int j = 0; j < 4; j++)
                acc[i][j] = fmaf(av[i], bv[j], acc[i][j]);
    }
    #pragma unroll
    for (int i = 0; i < 4; i++)
        *(float4*)&out[base + (r0+i)*NP + x0] =
            make_float4(acc[i][0], acc[i][1], acc[i][2], acc[i][3]);
}

// ---------------- S1: row DFT with Hermitian halving ------------------------
// Compute m = 0..32 only; T1[kept m] = direct, T1[64-m] = conj.
__global__ void __launch_bounds__(264, 2) k_dft_rows() {
    extern __shared__ __align__(16) float2 fy_s[];   // 33 x 264
    const int bc = blockIdx.x;
    const int tid = threadIdx.x;
    for (int idx = tid; idx < 33*HP; idx += 264) {
        int m = idx / HP, y = idx % HP;
        float2 f;
        if (m < 32) f = g_Fy[m*HP + y];
        else { f = g_Fy[32*HP + y]; f.y = -f.y; }   // ky=32 = conj(ky=232)
        fy_s[idx] = f;
    }
    __syncthreads();
    const int xt = tid % 66, rq = tid / 66;   // rq 0..3
    const int x0 = xt * 4, m0 = rq * 8;       // m groups {0..8},{8..16},{16..24},{24..32} (dup writes benign)
    const float* img = g_x + bc*NP;
    float ar[9][4], ai[9][4];
    #pragma unroll
    for (int r = 0; r < 9; r++)
        #pragma unroll
        for (int j = 0; j < 4; j++) { ar[r][j] = 0.f; ai[r][j] = 0.f; }
    for (int y = 0; y < HP; y++) {
        float4 v = *(const float4*)(img + y*HP + x0);
        const float vv[4] = {v.x, v.y, v.z, v.w};
        #pragma unroll
        for (int r = 0; r < 9; r++) {
            float2 f = fy_s[(m0 + r)*HP + y];
            #pragma unroll
            for (int j = 0; j < 4; j++) {
                ar[r][j] = fmaf(vv[j], f.x, ar[r][j]);
                ai[r][j] = fmaf(vv[j], f.y, ai[r][j]);
            }
        }
    }
    #pragma unroll
    for (int r = 0; r < 9; r++) {
        int m = m0 + r;
        if (m <= 31) {
            float2* dst = &g_T1[(bc*NR + m)*HP + x0];
            #pragma unroll
            for (int j = 0; j < 4; j++) dst[j] = make_float2(ar[r][j], ai[r][j]);
        }
        if (m >= 1) {
            float2* dst = &g_T1[(bc*NR + (64 - m))*HP + x0];
            #pragma unroll
            for (int j = 0; j < 4; j++) dst[j] = make_float2(ar[r][j], -ai[r][j]);
        }
    }
}

// ---------------- S2: col DFT: xf[r,k] = sum_x T1[r,x]*Fx[k,x] --------------
__global__ void __launch_bounds__(256) k_dft_cols() {
    __shared__ float2 t1s[16*HP];
    const int bc = blockIdx.x, rg = blockIdx.y;   // 16 r per block
    for (int idx = threadIdx.x; idx < 16*HP; idx += 256)
        t1s[idx] = g_T1[(bc*NR + rg*16)*HP + idx];
    __syncthreads();
    const int k = threadIdx.x & 31, rq = threadIdx.x >> 5;
    const int r0 = rq * 2;
    float a0r = 0.f, a0i = 0.f, a1r = 0.f, a1i = 0.f;
    for (int x = 0; x < HP; x++) {
        float2 f = __ldg(&g_FxT[x*NM + k]);
        float2 p = t1s[r0*HP + x];
        float2 q = t1s[(r0+1)*HP + x];
        a0r = fmaf(p.x, f.x, fmaf(-p.y, f.y, a0r));
        a0i = fmaf(p.x, f.y, fmaf( p.y, f.x, a0i));
        a1r = fmaf(q.x, f.x, fmaf(-q.y, f.y, a1r));
        a1i = fmaf(q.x, f.y, fmaf( q.y, f.x, a1i));
    }
    int r = rg*16 + r0;
    g_xf[(bc*NR + r    )*NM + k] = make_float2(a0r, a0i);
    g_xf[(bc*NR + r + 1)*NM + k] = make_float2(a1r, a1i);
}

// ---------------- S3: per-mode 64x64 complex channel mix -------------------
__global__ void __launch_bounds__(256) k_chanmix(
    const float* __restrict__ w1r, const float* __restrict__ w1i,
    const float* __restrict__ w2r, const float* __restrict__ w2i)
{
    int r = blockIdx.x >> 5, k = blockIdx.x & 31;
    __shared__ float wre[NC*NC];
    __shared__ float wim[NC*NC];
    __shared__ float2 xs[NB][NC];
    const float* wr; const float* wi; int m1;
    if (r < 32) { wr = w1r; wi = w1i; m1 = r; }
    else        { wr = w2r; wi = w2i; m1 = r - 32; }
    int woff = m1*32 + k;
    for (int idx = threadIdx.x; idx < NC*NC; idx += 256) {
        wre[idx] = wr[idx*1024 + woff];   // weight layout [i][o][32][32]
        wim[idx] = wi[idx*1024 + woff];
    }
    {
        int b = threadIdx.x >> 6, i = threadIdx.x & 63;
        xs[b][i] = g_xf[((b*NC + i)*NR + r)*NM + k];
    }
    __syncthreads();
    int o = threadIdx.x & 63, b = threadIdx.x >> 6;
    float ar = 0.f, ai = 0.f;
    #pragma unroll 4
    for (int i = 0; i < NC; i++) {
        float2 xv = xs[b][i];
        float wrv = wre[i*64 + o], wiv = wim[i*64 + o];
        ar += xv.x*wrv - xv.y*wiv;
        ai += xv.x*wiv + xv.y*wrv;
    }
    g_of[((b*NC + o)*NR + r)*NM + k] = make_float2(ar, ai);
}

// ---------------- S4: inverse DFT along ky (64 nonzero bins) ---------------
__global__ void __launch_bounds__(256) k_idft_rows() {
    __shared__ float2 os[NR*NM];
    const int bo = blockIdx.x;
    for (int idx = threadIdx.x; idx < NR*NM; idx += 256)
        os[idx] = g_of[bo*(NR*NM) + idx];
    __syncthreads();
    const int k = threadIdx.x & 31, yq = threadIdx.x >> 5;
    for (int it = 0; it < 9; it++) {
        int yg = yq + it*8;
        if (yg >= 66) return;
        int y0 = yg * 4;
        float ar[4] = {0,0,0,0}, ai[4] = {0,0,0,0};
        for (int r = 0; r < NR; r++) {
            float2 o = os[r*NM + k];
            const float2* fp = &g_Fy[r*HP + y0];
            float4 fA = __ldg((const float4*)fp);        // (c0,-s0,c1,-s1)
            float4 fB = __ldg((const float4*)(fp + 2));
            // inverse twiddle: ar += ox*c - oy*(-(-s)) -> ox*f.x + oy*f.y ; ai += oy*f.x - ox*f.y
            ar[0] = fmaf(o.x, fA.x, fmaf(o.y, fA.y, ar[0]));
            ai[0] = fmaf(o.y, fA.x, fmaf(-o.x, fA.y, ai[0]));
            ar[1] = fmaf(o.x, fA.z, fmaf(o.y, fA.w, ar[1]));
            ai[1] = fmaf(o.y, fA.z, fmaf(-o.x, fA.w, ai[1]));
            ar[2] = fmaf(o.x, fB.x, fmaf(o.y, fB.y, ar[2]));
            ai[2] = fmaf(o.y, fB.x, fmaf(-o.x, fB.y, ai[2]));
            ar[3] = fmaf(o.x, fB.z, fmaf(o.y, fB.w, ar[3]));
            ai[3] = fmaf(o.y, fB.z, fmaf(-o.x, fB.w, ai[3]));
        }
        #pragma unroll
        for (int j = 0; j < 4; j++)
            g_U[(bo*HP + y0 + j)*NM + k] = make_float2(ar[j]*INV_HP, ai[j]*INV_HP);
    }
}

// ---------------- S5: real inverse along kx + add local branch (+crop) -----
template<bool LAST>
__global__ void __launch_bounds__(264) k_idft_cols_add(float* __restrict__ out) {
    __shared__ float2 us[4*NM];
    const int bo = blockIdx.y, yt = blockIdx.x;
    const int tid = threadIdx.x;
    if (tid < 128) {
        int yl = tid >> 5, k = tid & 31;
        us[tid] = g_U[(bo*HP + yt*4 + yl)*NM + k];
    }
    __syncthreads();
    const int xt = tid % 66, yq = tid / 66;
    const int x0 = xt * 4, y = yt * 4 + yq;
    float s[4];
    {
        float u0 = us[yq*NM].x;
        s[0] = u0; s[1] = u0; s[2] = u0; s[3] = u0;
    }
    for (int k = 1; k < NM; k++) {
        float2 u = us[yq*NM + k];
        const float2* fp = &g_Fx[k*HP + x0];
        float4 fA = __ldg((const float4*)fp);
        float4 fB = __ldg((const float4*)(fp + 2));
        // s += 2*(Re*cos - Im*sin) ; f = (cos,-sin)
        s[0] = fmaf(2.f*u.x, fA.x, fmaf(2.f*u.y, fA.y, s[0]));
        s[1] = fmaf(2.f*u.x, fA.z, fmaf(2.f*u.y, fA.w, s[1]));
        s[2] = fmaf(2.f*u.x, fB.x, fmaf(2.f*u.y, fB.y, s[2]));
        s[3] = fmaf(2.f*u.x, fB.z, fmaf(2.f*u.y, fB.w, s[3]));
    }
    const int idx = bo*NP + y*HP + x0;
    float4 h = *(const float4*)&g_hbr[idx];
    float4 res = make_float4(h.x + s[0]*INV_HP, h.y + s[1]*INV_HP,
                             h.z + s[2]*INV_HP, h.w + s[3]*INV_HP);
    if (LAST) {
        if (y < H0 && x0 < W0)
            *(float4*)&out[bo*NPIX0 + y*W0 + x0] = res;
    } else {
        *(float4*)&g_x[idx] = res;
    }
}

// ---------------- launch -----------------------------------------------------
extern "C" void kernel_launch(void* const* d_in, const int* in_sizes, int n_in,
                              void* d_out, int out_size)
{
    const float* x   = (const float*)d_in[0];
    const float* lw1 = (const float*)d_in[1];
    const float* lb1 = (const float*)d_in[2];
    const float* lw2 = (const float*)d_in[3];
    const float* lb2 = (const float*)d_in[4];
    const float* cw  = (const float*)d_in[5];
    const float* cb  = (const float*)d_in[6];
    const float* m1w = (const float*)d_in[7];
    const float* m1b = (const float*)d_in[8];
    const float* m2w = (const float*)d_in[9];
    const float* m2b = (const float*)d_in[10];
    const float* s1r = (const float*)d_in[11];
    const float* s1i = (const float*)d_in[12];
    const float* s2r = (const float*)d_in[13];
    const float* s2i = (const float*)d_in[14];
    float* out = (float*)d_out;

    float *px, *ph;
    cudaGetSymbolAddress((void**)&px, g_x);
    cudaGetSymbolAddress((void**)&ph, g_hbr);

    const int LOCAL_SMEM = 25088 * 4;   // 100352 B
    const int DFTR_SMEM  = 33 * HP * 8; // 69696 B
    cudaFuncSetAttribute(k_local,    cudaFuncAttributeMaxDynamicSharedMemorySize, LOCAL_SMEM);
    cudaFuncSetAttribute(k_dft_rows, cudaFuncAttributeMaxDynamicSharedMemorySize, DFTR_SMEM);

    k_tables<<<132, 256>>>();
    k_zero_x<<<4096, 256>>>();
    k_lift<<<dim3(256, NB), 256>>>(x, lw1, lb1, lw2, lb2);

    for (int L = 0; L < 3; L++) {
        k_local<<<dim3(NP/64, NB), 256, LOCAL_SMEM>>>(
            px, ph,
            cw  + L*64*64,   cb  + L*64,
            m1w + L*128*64,  m1b + L*128,
            m2w + L*64*128,  m2b + L*64);
        k_dft_rows<<<NB*NC, 264, DFTR_SMEM>>>();
        k_dft_cols<<<dim3(NB*NC, 4), 256>>>();
        k_chanmix<<<NR*NM, 256>>>(s1r + L*SPW, s1i + L*SPW, s2r + L*SPW, s2i + L*SPW);
        k_idft_rows<<<NB*NC, 256>>>();
        if (L < 2) k_idft_cols_add<false><<<dim3(66, NB*NC), 264>>>(out);
        else       k_idft_cols_add<true ><<<dim3(66, NB*NC), 264>>>(out);
    }
}